// round 5
// baseline (speedup 1.0000x reference)
#include <cuda_runtime.h>
#include <math.h>

#define HH 512
#define WW 512
#define NB 32
#define MS 10
#define SH 21            // 2*MS+1
#define NS 441           // SH*SH
#define NPIX (HH*WW)     // 262144
#define KAREA (492.0*492.0)
#define EPS 1e-8

#define TB 16                    // rows per correlation band
#define NBAND (HH/TB)            // 32
#define TROWS (TB + 20)          // 36
#define TCB 532                  // template cols (bf16); row stride 1064B (8B-aligned)
#define ISTR 516                 // image row stride in floats (2064B, 16B-aligned)
#define CORR_THREADS 336         // 21 p-values x 16 rows
#define SMEM_CORR (TROWS*TCB*2 + TB*ISTR*4)   // 38304 + 33024 = 71328
#define SMEM_STATS (40*512*4)

// ---------------- scratch ----------------
__device__ double g_tstats[2];
__device__ double g_isum[NB];
__device__ double g_colF1[NB*WW];
__device__ double g_colF2[NB*WW];
__device__ float  g_den[NB*NS];
__device__ float  g_ccpart[NB*NBAND*NS];
__device__ float  g_shift[NB*2];

// ---------------- K0: zero atomic targets ----------------
__global__ void k_zero() {
    int i = blockIdx.x * blockDim.x + threadIdx.x;
    if (i < NB * WW) { g_colF1[i] = 0.0; g_colF2[i] = 0.0; }
    if (i < 2) g_tstats[i] = 0.0;
}

// ---------------- K1: column partial sums + template stats ----------------
__global__ void k_colpart(const float* __restrict__ fr, const float* __restrict__ tp) {
    int b = blockIdx.x;
    int slab = blockIdx.y;
    int x = threadIdx.x;
    const float* src = (b < NB) ? (fr + (size_t)b * NPIX) : tp;
    int y0 = slab * 64;
    float s1a = 0.f, s1b = 0.f, s2a = 0.f, s2b = 0.f;
#pragma unroll 4
    for (int y = y0; y < y0 + 64; y += 2) {
        float v0 = src[y * WW + x];
        float v1 = src[(y + 1) * WW + x];
        s1a += v0; s1b += v1;
        s2a = fmaf(v0, v0, s2a); s2b = fmaf(v1, v1, s2b);
    }
    double d1 = (double)s1a + (double)s1b;
    double d2 = (double)s2a + (double)s2b;
    if (b < NB) {
        atomicAdd(&g_colF1[b * WW + x], d1);
        atomicAdd(&g_colF2[b * WW + x], d2);
    } else {
        __shared__ double r1[512], r2[512];
        r1[x] = d1; r2[x] = d2;
        __syncthreads();
        for (int st = 256; st > 0; st >>= 1) {
            if (x < st) { r1[x] += r1[x + st]; r2[x] += r2[x + st]; }
            __syncthreads();
        }
        if (x == 0) {
            atomicAdd(&g_tstats[0], r1[0]);
            atomicAdd(&g_tstats[1], r2[0]);
        }
    }
}

// ---------------- K2: all 441 window denominators per frame ----------------
__global__ void k_stats(const float* __restrict__ fr) {
    __shared__ double scol1[512], scol2[512];
    __shared__ double srow1[40], srow2[40];
    __shared__ double rowPre1[41], rowPre2[41];
    __shared__ double colPre1[21], colPre2[21];
    __shared__ double colSuf1[21], colSuf2[21];
    __shared__ double spart1[16], spart2[16];
    __shared__ double sS1s, sS2s;
    __shared__ float PP1[41*41], PP2[41*41];
    extern __shared__ float sedge[];         // 40*512

    int b = blockIdx.x, tid = threadIdx.x;   // 512 threads
    scol1[tid] = g_colF1[b * WW + tid];
    scol2[tid] = g_colF2[b * WW + tid];
    const float* im = fr + (size_t)b * NPIX;
    for (int idx = tid; idx < 40 * 512; idx += 512) {
        int r = idx >> 9, c = idx & 511;
        int y = (r < 20) ? r : (472 + r);
        sedge[idx] = im[y * WW + c];
    }
    __syncthreads();

    int wid = tid >> 5, lane = tid & 31;
    for (int r = wid; r < 40; r += 16) {
        double a = 0.0, c2 = 0.0;
        for (int c = lane; c < 512; c += 32) {
            double v = (double)sedge[r * 512 + c];
            a += v; c2 += v * v;
        }
#pragma unroll
        for (int s = 16; s > 0; s >>= 1) {
            a  += __shfl_down_sync(0xffffffffu, a, s);
            c2 += __shfl_down_sync(0xffffffffu, c2, s);
        }
        if (lane == 0) { srow1[r] = a; srow2[r] = c2; }
    }
    for (int idx = tid; idx < 41 * 41; idx += 512) { PP1[idx] = 0.f; PP2[idx] = 0.f; }
    __syncthreads();

    for (int idx = tid; idx < 1600; idx += 512) {
        int r = idx / 40, cc = idx - r * 40;
        int col = (cc < 20) ? cc : (472 + cc);
        float v = sedge[r * 512 + col];
        PP1[(r + 1) * 41 + cc + 1] = v;
        PP2[(r + 1) * 41 + cc + 1] = v * v;
    }
    {
        double a = scol1[tid], c2 = scol2[tid];
#pragma unroll
        for (int s = 16; s > 0; s >>= 1) {
            a  += __shfl_down_sync(0xffffffffu, a, s);
            c2 += __shfl_down_sync(0xffffffffu, c2, s);
        }
        if (lane == 0) { spart1[wid] = a; spart2[wid] = c2; }
    }
    __syncthreads();

    if (tid < 41) {
        float a = 0.f, c2 = 0.f;
        for (int c = 0; c < 41; ++c) {
            a  += PP1[tid * 41 + c]; PP1[tid * 41 + c] = a;
            c2 += PP2[tid * 41 + c]; PP2[tid * 41 + c] = c2;
        }
    }
    if (tid == 64)  { double a = 0; rowPre1[0] = 0; for (int r = 0; r < 40; ++r) { a += srow1[r]; rowPre1[r+1] = a; } }
    if (tid == 96)  { double a = 0; rowPre2[0] = 0; for (int r = 0; r < 40; ++r) { a += srow2[r]; rowPre2[r+1] = a; } }
    if (tid == 128) { double a = 0; colPre1[0] = 0; for (int c = 0; c < 20; ++c) { a += scol1[c]; colPre1[c+1] = a; } }
    if (tid == 160) { double a = 0; colPre2[0] = 0; for (int c = 0; c < 20; ++c) { a += scol2[c]; colPre2[c+1] = a; } }
    if (tid == 192) { double a = 0; colSuf1[20] = 0; for (int j = 19; j >= 0; --j) { a += scol1[492+j]; colSuf1[j] = a; } }
    if (tid == 224) { double a = 0; colSuf2[20] = 0; for (int j = 19; j >= 0; --j) { a += scol2[492+j]; colSuf2[j] = a; } }
    if (tid == 256) { double a = 0; for (int w = 0; w < 16; ++w) a += spart1[w]; sS1s = a; g_isum[b] = a; }
    if (tid == 288) { double a = 0; for (int w = 0; w < 16; ++w) a += spart2[w]; sS2s = a; }
    __syncthreads();

    if (tid < 41) {
        float a = 0.f, c2 = 0.f;
        for (int r = 0; r < 41; ++r) {
            a  += PP1[r * 41 + tid]; PP1[r * 41 + tid] = a;
            c2 += PP2[r * 41 + tid]; PP2[r * 41 + tid] = c2;
        }
    }
    __syncthreads();

#define RECT(PP, r0, r1, c0, c1) \
    (PP[(r1)*41+(c1)] - PP[(r0)*41+(c1)] - PP[(r1)*41+(c0)] + PP[(r0)*41+(c0)])
    if (tid < NS) {
        int p = tid / SH, j = tid - p * SH;
        double rsum1 = rowPre1[p] + (rowPre1[40] - rowPre1[p + 20]);
        double rsum2 = rowPre2[p] + (rowPre2[40] - rowPre2[p + 20]);
        double csum1 = colPre1[j] + colSuf1[j];
        double csum2 = colPre2[j] + colSuf2[j];
        float q1 = RECT(PP1, 0, p, 0, j) + RECT(PP1, 0, p, 20 + j, 40)
                 + RECT(PP1, p + 20, 40, 0, j) + RECT(PP1, p + 20, 40, 20 + j, 40);
        float q2 = RECT(PP2, 0, p, 0, j) + RECT(PP2, 0, p, 20 + j, 40)
                 + RECT(PP2, p + 20, 40, 0, j) + RECT(PP2, p + 20, 40, 20 + j, 40);
        double w1 = sS1s - rsum1 - csum1 + (double)q1;
        double w2 = sS2s - rsum2 - csum2 + (double)q2;
        double m1 = w1 / KAREA;
        double m2 = w2 / KAREA;
        double var = m2 - m1 * m1 / KAREA + EPS;
        float vf = (float)var;
        if (vf < 0.f) vf = 0.f;
        float tvar = (float)(g_tstats[1] - g_tstats[0] * g_tstats[0] / (double)NPIX + EPS);
        g_den[(size_t)b * NS + tid] = sqrtf(tvar * vf);
    }
#undef RECT
}

// ---------------- K3: the correlation (hot kernel) ----------------
__device__ __forceinline__ unsigned f2bf(float v) {
    unsigned u = __float_as_uint(v);
    return (u + 0x7fffu + ((u >> 16) & 1u)) >> 16;
}

template<int U>
__device__ __forceinline__ void sgstep(const unsigned short* __restrict__ tpr,
                                       const float* __restrict__ ip,
                                       float win[28], float acc[SH]) {
    const int X = 4 * U;
    uint2 tw = *(const uint2*)(tpr + X + 24);          // T[x+24..x+27] as bf16
    float4 cur = *(const float4*)(ip + X);
    const int rs = (4 * U + 24) % 28;                   // slots dead since last step
    win[rs]            = __uint_as_float(tw.x << 16);
    win[(rs + 1) % 28] = __uint_as_float(tw.x & 0xffff0000u);
    win[(rs + 2) % 28] = __uint_as_float(tw.y << 16);
    win[(rs + 3) % 28] = __uint_as_float(tw.y & 0xffff0000u);
#pragma unroll
    for (int j = 0; j < SH; ++j) acc[j] = fmaf(cur.x, win[(4*U + 20 - j) % 28], acc[j]);
#pragma unroll
    for (int j = 0; j < SH; ++j) acc[j] = fmaf(cur.y, win[(4*U + 21 - j) % 28], acc[j]);
#pragma unroll
    for (int j = 0; j < SH; ++j) acc[j] = fmaf(cur.z, win[(4*U + 22 - j) % 28], acc[j]);
#pragma unroll
    for (int j = 0; j < SH; ++j) acc[j] = fmaf(cur.w, win[(4*U + 23 - j) % 28], acc[j]);
}

__global__ void __launch_bounds__(CORR_THREADS, 3)
k_corr(const float* __restrict__ fr, const float* __restrict__ tp) {
    int b = blockIdx.x;
    int band = blockIdx.y;
    int y0 = band * TB;
    extern __shared__ float sm[];
    unsigned short* sm_t = (unsigned short*)sm;        // TROWS x TCB  (bf16)
    float* sm_i = sm + (TROWS * TCB) / 2;              // TB x ISTR    (fp32)
    int tid = threadIdx.x;

    for (int idx = tid; idx < TROWS * TCB; idx += CORR_THREADS) {
        int r = idx / TCB, c = idx - r * TCB;
        float v = tp[((y0 - MS + r) & (HH - 1)) * WW + ((c - MS) & (WW - 1))];
        sm_t[idx] = (unsigned short)f2bf(v);
    }
    const float* im = fr + (size_t)b * NPIX + (size_t)y0 * WW;
    for (int idx = tid; idx < TB * WW; idx += CORR_THREADS) {
        int r = idx >> 9, c = idx & (WW - 1);
        sm_i[r * ISTR + c] = im[idx];
    }
    __syncthreads();

    int yl = tid & 15;
    int p  = tid >> 4;
    const unsigned short* tpr = sm_t + (yl + 2 * MS - p) * TCB;
    const float* ip = sm_i + yl * ISTR;

    float acc[SH];
#pragma unroll
    for (int j = 0; j < SH; ++j) acc[j] = 0.f;

    float win[28];
#pragma unroll
    for (int w = 0; w < 6; ++w) {                       // fill slots 0..23 = T[0..23]
        uint2 tw = *(const uint2*)(tpr + 4 * w);
        win[4*w + 0] = __uint_as_float(tw.x << 16);
        win[4*w + 1] = __uint_as_float(tw.x & 0xffff0000u);
        win[4*w + 2] = __uint_as_float(tw.y << 16);
        win[4*w + 3] = __uint_as_float(tw.y & 0xffff0000u);
    }

#pragma unroll 1
    for (int it = 0; it < 18; ++it) {                   // 18 x 28 = 504 pixels
        sgstep<0>(tpr, ip, win, acc);
        sgstep<1>(tpr, ip, win, acc);
        sgstep<2>(tpr, ip, win, acc);
        sgstep<3>(tpr, ip, win, acc);
        sgstep<4>(tpr, ip, win, acc);
        sgstep<5>(tpr, ip, win, acc);
        sgstep<6>(tpr, ip, win, acc);
        tpr += 28; ip += 28;
    }
    sgstep<0>(tpr, ip, win, acc);                       // x = 504
    sgstep<1>(tpr, ip, win, acc);                       // x = 508 (tail refill reads pad; unused)
    __syncthreads();

    float* sred = sm;                                   // reuse: 441*16 floats (28KB < 71KB)
#pragma unroll
    for (int j = 0; j < SH; ++j) sred[(p * SH + j) * 16 + yl] = acc[j];
    __syncthreads();
    for (int s = tid; s < NS; s += CORR_THREADS) {
        float v = 0.f;
#pragma unroll
        for (int k = 0; k < 16; ++k) v += sred[s * 16 + k];
        g_ccpart[((size_t)b * NBAND + band) * NS + s] = v;
    }
}

// ---------------- K4: ncc, argmax, subpixel shift ----------------
__global__ void k_peak() {
    int b = blockIdx.x, tid = threadIdx.x;
    __shared__ float sncc[NS];
    __shared__ float rv[512];
    __shared__ int   ri[512];
    float cfix = (float)(g_isum[b] * g_tstats[0] / (double)NPIX);
    if (tid < NS) {
        float s = 0.f;
        for (int k = 0; k < NBAND; ++k)
            s += g_ccpart[((size_t)b * NBAND + k) * NS + tid];
        float ccv = fabsf(s - cfix);
        float v = ccv / g_den[(size_t)b * NS + tid];
        if (!(v == v)) v = 0.f;
        sncc[tid] = v;
    }
    __syncthreads();
    rv[tid] = (tid < NS) ? sncc[tid] : -1.f;
    ri[tid] = tid;
    __syncthreads();
    for (int st = 256; st > 0; st >>= 1) {
        if (tid < st) {
            float ov = rv[tid + st]; int oi = ri[tid + st];
            if (ov > rv[tid] || (ov == rv[tid] && oi < ri[tid])) { rv[tid] = ov; ri[tid] = oi; }
        }
        __syncthreads();
    }
    if (tid == 0) {
        int am = ri[0];
        int sx = am / SH, sy = am - sx * SH;
        float shx = -(float)(sx - MS);
        float shy = -(float)(sy - MS);
        int xm = sx - 1; if (xm < 0) xm += SH;
        int xp = sx + 1; if (xp > SH - 1) xp = SH - 1;
        int ym = sy - 1; if (ym < 0) ym += SH;
        int yp = sy + 1; if (yp > SH - 1) yp = SH - 1;
        float lxm = logf(sncc[xm * SH + sy]);
        float lxp = logf(sncc[xp * SH + sy]);
        float lym = logf(sncc[sx * SH + ym]);
        float lyp = logf(sncc[sx * SH + yp]);
        float lc4 = 4.f * logf(sncc[sx * SH + sy]);
        shx -= (lxm - lxp) / (2.f * lxm - lc4 + 2.f * lxp);
        shy -= (lym - lyp) / (2.f * lym - lc4 + 2.f * lyp);
        g_shift[b * 2 + 0] = shx;
        g_shift[b * 2 + 1] = shy;
    }
}

// ---------------- K5: bilinear warp + transposed store ----------------
__global__ void k_warp(const float* __restrict__ fr, float* __restrict__ out) {
    int b = blockIdx.z;
    int X0 = blockIdx.x * 32, Y0 = blockIdx.y * 32;
    float dy = g_shift[b * 2 + 0];
    float dx = g_shift[b * 2 + 1];
    __shared__ float sp[36 * 37];
    int ry = Y0 + (int)floorf(-dy) - 1;
    int rx = X0 + (int)floorf(-dx) - 1;
    const float* im = fr + (size_t)b * NPIX;
    for (int idx = threadIdx.x; idx < 36 * 36; idx += 256) {
        int r = idx / 36, c = idx - r * 36;
        int gy = ry + r, gx = rx + c;
        float v = (gy >= 0 && gy < HH && gx >= 0 && gx < WW) ? im[gy * WW + gx] : 0.f;
        sp[r * 37 + c] = v;
    }
    __syncthreads();
    int oy = threadIdx.x & 31;
    int oxb = threadIdx.x >> 5;
    for (int k = 0; k < 4; ++k) {
        int ox = oxb + 8 * k;
        int y = Y0 + oy, x = X0 + ox;
        float yq = (float)y - dy; float y0f = floorf(yq); float wy = yq - y0f;
        float xq = (float)x - dx; float x0f = floorf(xq); float wx = xq - x0f;
        int iy = (int)y0f - ry; int ix = (int)x0f - rx;
        iy = max(0, min(34, iy)); ix = max(0, min(34, ix));
        float v00 = sp[iy * 37 + ix];
        float v01 = sp[iy * 37 + ix + 1];
        float v10 = sp[(iy + 1) * 37 + ix];
        float v11 = sp[(iy + 1) * 37 + ix + 1];
        float val = v00 * (1.f - wy) * (1.f - wx) + v01 * (1.f - wy) * wx
                  + v10 * wy * (1.f - wx) + v11 * wy * wx;
        out[(size_t)b * NPIX + x * HH + y] = val;
    }
}

// ---------------- launch ----------------
extern "C" void kernel_launch(void* const* d_in, const int* in_sizes, int n_in,
                              void* d_out, int out_size) {
    const float* fr = (const float*)d_in[0];
    const float* tp = (const float*)d_in[1];
    if (n_in >= 2 && in_sizes[0] < in_sizes[1]) { const float* t = fr; fr = tp; tp = t; }
    float* out = (float*)d_out;

    cudaFuncSetAttribute(k_corr,  cudaFuncAttributeMaxDynamicSharedMemorySize, SMEM_CORR);
    cudaFuncSetAttribute(k_stats, cudaFuncAttributeMaxDynamicSharedMemorySize, SMEM_STATS);

    k_zero<<<64, 512>>>();
    k_colpart<<<dim3(NB + 1, 8), 512>>>(fr, tp);
    k_stats<<<NB, 512, SMEM_STATS>>>(fr);
    k_corr<<<dim3(NB, NBAND), CORR_THREADS, SMEM_CORR>>>(fr, tp);
    k_peak<<<NB, 512>>>();
    k_warp<<<dim3(16, 16, NB), 256>>>(fr, out);
}